// round 4
// baseline (speedup 1.0000x reference)
#include <cuda_runtime.h>
#include <cstdint>

#define BATCH 8
#define SEQ   1024
#define DMODEL 512
#define NHEAD 8
#define HDIM  64

#define BM 64
#define BN 64
#define BKK 16

static __device__ float g_qu [(size_t)BATCH*NHEAD*SEQ*HDIM];
static __device__ float g_qvb[(size_t)BATCH*NHEAD*SEQ*HDIM];
static __device__ float g_kh [(size_t)BATCH*NHEAD*SEQ*HDIM];
static __device__ float g_vh [(size_t)BATCH*NHEAD*SEQ*HDIM];
static __device__ float g_ph [(size_t)BATCH*NHEAD*SEQ*HDIM];
static __device__ float g_ctx[(size_t)BATCH*SEQ*DMODEL];
static __device__ float g_pos[(size_t)BATCH*NHEAD*SEQ*SEQ];

// ---------------------------------------------------------------------------
// NT projection GEMM: Y[m,j] = sum_d X[m,d]*W[j,d] (+ bias[j])
// Output scattered to head-major [b][n][s][hd]. Optionally dual output
// (O1 = Y + add1[j], O2 = Y + add2[j]) for the q projection.
// ---------------------------------------------------------------------------
__global__ __launch_bounds__(256)
void k_proj(const float* __restrict__ X, const float* __restrict__ W,
            const float* __restrict__ bias,
            float* __restrict__ O1, const float* __restrict__ add1,
            float* __restrict__ O2, const float* __restrict__ add2)
{
    __shared__ float As[BKK][BM + 4];
    __shared__ float Bs[BKK][BN + 4];
    const int K = DMODEL;
    const int tid = threadIdx.x;
    const int m0 = blockIdx.y * BM;
    const int n0 = blockIdx.x * BN;
    const int tx = tid & 15, ty = tid >> 4;
    const int lrow = tid >> 2, lk = (tid & 3) * 4;

    const float* Aptr = X + (size_t)(m0 + lrow) * K + lk;
    const float* Bptr = W + (size_t)(n0 + lrow) * K + lk;

    float acc[4][4] = {};
    for (int k0 = 0; k0 < K; k0 += BKK) {
        float4 a4 = *(const float4*)(Aptr + k0);
        float4 b4 = *(const float4*)(Bptr + k0);
        As[lk + 0][lrow] = a4.x; As[lk + 1][lrow] = a4.y;
        As[lk + 2][lrow] = a4.z; As[lk + 3][lrow] = a4.w;
        Bs[lk + 0][lrow] = b4.x; Bs[lk + 1][lrow] = b4.y;
        Bs[lk + 2][lrow] = b4.z; Bs[lk + 3][lrow] = b4.w;
        __syncthreads();
#pragma unroll
        for (int kk = 0; kk < BKK; kk++) {
            float4 av = *(const float4*)&As[kk][ty * 4];
            float4 bv = *(const float4*)&Bs[kk][tx * 4];
            float a[4] = {av.x, av.y, av.z, av.w};
            float b[4] = {bv.x, bv.y, bv.z, bv.w};
#pragma unroll
            for (int i = 0; i < 4; i++)
#pragma unroll
                for (int j = 0; j < 4; j++) acc[i][j] += a[i] * b[j];
        }
        __syncthreads();
    }

#pragma unroll
    for (int i = 0; i < 4; i++) {
        int m = m0 + ty * 4 + i;
        int bb = m >> 10, s = m & (SEQ - 1);
#pragma unroll
        for (int j = 0; j < 4; j++) {
            int jj = n0 + tx * 4 + j;
            int n = jj >> 6, hd = jj & (HDIM - 1);
            float v = acc[i][j];
            if (bias) v += bias[jj];
            size_t off = (((size_t)bb * NHEAD + n) * SEQ + s) * HDIM + hd;
            float v1 = v;
            if (add1) v1 += add1[jj];
            O1[off] = v1;
            if (O2) O2[off] = v + add2[jj];
        }
    }
}

// ---------------------------------------------------------------------------
// Batched score GEMM (NT, K=64): C[q,k] = sum_d A[q,d]*B[k,d].
// z in [0,64): content scores (qu x kh) -> C0 ; z in [64,128): pos (qvb x ph) -> C1
// ---------------------------------------------------------------------------
__global__ __launch_bounds__(256)
void k_scores(const float* __restrict__ A0, const float* __restrict__ B0,
              float* __restrict__ C0,
              const float* __restrict__ A1, const float* __restrict__ B1,
              float* __restrict__ C1)
{
    __shared__ float As[BKK][BM + 4];
    __shared__ float Bs[BKK][BN + 4];
    int z = blockIdx.z;
    const float *Aall, *Ball; float* Call;
    if (z < BATCH * NHEAD) { Aall = A0; Ball = B0; Call = C0; }
    else { z -= BATCH * NHEAD; Aall = A1; Ball = B1; Call = C1; }
    const float* X = Aall + (size_t)z * SEQ * HDIM;
    const float* W = Ball + (size_t)z * SEQ * HDIM;
    float* C = Call + (size_t)z * SEQ * SEQ;

    const int tid = threadIdx.x;
    const int m0 = blockIdx.y * BM;
    const int n0 = blockIdx.x * BN;
    const int tx = tid & 15, ty = tid >> 4;
    const int lrow = tid >> 2, lk = (tid & 3) * 4;

    const float* Aptr = X + (size_t)(m0 + lrow) * HDIM + lk;
    const float* Bptr = W + (size_t)(n0 + lrow) * HDIM + lk;

    float acc[4][4] = {};
#pragma unroll
    for (int k0 = 0; k0 < HDIM; k0 += BKK) {
        float4 a4 = *(const float4*)(Aptr + k0);
        float4 b4 = *(const float4*)(Bptr + k0);
        As[lk + 0][lrow] = a4.x; As[lk + 1][lrow] = a4.y;
        As[lk + 2][lrow] = a4.z; As[lk + 3][lrow] = a4.w;
        Bs[lk + 0][lrow] = b4.x; Bs[lk + 1][lrow] = b4.y;
        Bs[lk + 2][lrow] = b4.z; Bs[lk + 3][lrow] = b4.w;
        __syncthreads();
#pragma unroll
        for (int kk = 0; kk < BKK; kk++) {
            float4 av = *(const float4*)&As[kk][ty * 4];
            float4 bv = *(const float4*)&Bs[kk][tx * 4];
            float a[4] = {av.x, av.y, av.z, av.w};
            float b[4] = {bv.x, bv.y, bv.z, bv.w};
#pragma unroll
            for (int i = 0; i < 4; i++)
#pragma unroll
                for (int j = 0; j < 4; j++) acc[i][j] += a[i] * b[j];
        }
        __syncthreads();
    }

#pragma unroll
    for (int i = 0; i < 4; i++) {
        int m = m0 + ty * 4 + i;
#pragma unroll
        for (int j = 0; j < 4; j++) {
            int kcol = n0 + tx * 4 + j;
            C[(size_t)m * SEQ + kcol] = acc[i][j];
        }
    }
}

// ---------------------------------------------------------------------------
// Fused relative shift + scale + mask + softmax. One block per (b,n,q) row.
// content lives in AttnOut (in-place update), pos in g_pos.
// shift[q,k] = pos[q, S-1-q+k]      (k <= q)
//            = 0                    (k == q+1)
//            = pos[q+1, k-q-2]      (k >  q+1)
// Mask is int32 (harness converts bool inputs to int32).
// ---------------------------------------------------------------------------
__global__ __launch_bounds__(256)
void k_softmax(float* __restrict__ AttnOut, const float* __restrict__ Pos,
               const int* __restrict__ Mask)
{
    const int row = blockIdx.x;          // ((b*NHEAD + n)*SEQ + q)
    const int q = row & (SEQ - 1);
    const int z = row >> 10;             // b*NHEAD + n
    const int b = z >> 3;

    float* Crow = AttnOut + (size_t)row * SEQ;
    const float* P0 = Pos + ((size_t)z * SEQ + q) * SEQ;
    const float* P1 = Pos + ((size_t)z * SEQ + q + 1) * SEQ;  // used only if k>q+1
    const int* Mrow = Mask + ((size_t)b * SEQ + q) * SEQ;

    const float scale = 0.04419417382415922f;  // 1/sqrt(512)
    const int tid = threadIdx.x;

    float vals[4];
    float lmax = -3.0e38f;
#pragma unroll
    for (int i = 0; i < 4; i++) {
        int k = tid + i * 256;
        float c = Crow[k];
        float p;
        if (k <= q)           p = P0[SEQ - 1 - q + k];
        else if (k == q + 1)  p = 0.0f;
        else                  p = P1[k - q - 2];
        float sc = (c + p) * scale;
        if (Mrow[k] != 0) sc = -10000.0f;
        vals[i] = sc;
        lmax = fmaxf(lmax, sc);
    }

    __shared__ float red[8];
#pragma unroll
    for (int o = 16; o; o >>= 1) lmax = fmaxf(lmax, __shfl_xor_sync(0xffffffffu, lmax, o));
    if ((tid & 31) == 0) red[tid >> 5] = lmax;
    __syncthreads();
    float bmax = red[0];
#pragma unroll
    for (int w = 1; w < 8; w++) bmax = fmaxf(bmax, red[w]);

    float lsum = 0.0f;
#pragma unroll
    for (int i = 0; i < 4; i++) {
        vals[i] = __expf(vals[i] - bmax);
        lsum += vals[i];
    }
#pragma unroll
    for (int o = 16; o; o >>= 1) lsum += __shfl_xor_sync(0xffffffffu, lsum, o);
    __syncthreads();
    if ((tid & 31) == 0) red[tid >> 5] = lsum;
    __syncthreads();
    float tot = 0.0f;
#pragma unroll
    for (int w = 0; w < 8; w++) tot += red[w];
    float inv = 1.0f / tot;

#pragma unroll
    for (int i = 0; i < 4; i++) {
        int k = tid + i * 256;
        Crow[k] = vals[i] * inv;
    }
}

// ---------------------------------------------------------------------------
// Batched AV GEMM (NN): Ctx[b][q][n*HDIM+d] = sum_k attn[z][q][k]*vh[z][k][d]
// ---------------------------------------------------------------------------
__global__ __launch_bounds__(256)
void k_av(const float* __restrict__ Attn, const float* __restrict__ Vall,
          float* __restrict__ Ctx)
{
    __shared__ float As[BKK][BM + 4];
    __shared__ float Bs[BKK][BN];
    const int z = blockIdx.z;
    const int b = z >> 3, n = z & 7;
    const float* Ab = Attn + (size_t)z * SEQ * SEQ;
    const float* Bb = Vall + (size_t)z * SEQ * HDIM;

    const int tid = threadIdx.x;
    const int m0 = blockIdx.y * BM;
    const int tx = tid & 15, ty = tid >> 4;
    const int lrow = tid >> 2, lk = (tid & 3) * 4;
    const int brow = tid >> 4, bcol = (tid & 15) * 4;

    float acc[4][4] = {};
    for (int k0 = 0; k0 < SEQ; k0 += BKK) {
        float4 a4 = *(const float4*)(Ab + (size_t)(m0 + lrow) * SEQ + k0 + lk);
        As[lk + 0][lrow] = a4.x; As[lk + 1][lrow] = a4.y;
        As[lk + 2][lrow] = a4.z; As[lk + 3][lrow] = a4.w;
        float4 b4 = *(const float4*)(Bb + (size_t)(k0 + brow) * HDIM + bcol);
        *(float4*)&Bs[brow][bcol] = b4;
        __syncthreads();
#pragma unroll
        for (int kk = 0; kk < BKK; kk++) {
            float4 av = *(const float4*)&As[kk][ty * 4];
            float4 bv = *(const float4*)&Bs[kk][tx * 4];
            float a[4] = {av.x, av.y, av.z, av.w};
            float bvv[4] = {bv.x, bv.y, bv.z, bv.w};
#pragma unroll
            for (int i = 0; i < 4; i++)
#pragma unroll
                for (int j = 0; j < 4; j++) acc[i][j] += a[i] * bvv[j];
        }
        __syncthreads();
    }

#pragma unroll
    for (int i = 0; i < 4; i++) {
        int qrow = m0 + ty * 4 + i;
#pragma unroll
        for (int j = 0; j < 4; j++) {
            int d = tx * 4 + j;
            Ctx[((size_t)b * SEQ + qrow) * DMODEL + n * HDIM + d] = acc[i][j];
        }
    }
}

// ---------------------------------------------------------------------------
// Output NT GEMM: Out[m,j] = sum_d Ctx[m,d]*Wout[j,d] + bout[j] (row-major)
// ---------------------------------------------------------------------------
__global__ __launch_bounds__(256)
void k_out(const float* __restrict__ X, const float* __restrict__ W,
           const float* __restrict__ bias, float* __restrict__ Out)
{
    __shared__ float As[BKK][BM + 4];
    __shared__ float Bs[BKK][BN + 4];
    const int K = DMODEL;
    const int tid = threadIdx.x;
    const int m0 = blockIdx.y * BM;
    const int n0 = blockIdx.x * BN;
    const int tx = tid & 15, ty = tid >> 4;
    const int lrow = tid >> 2, lk = (tid & 3) * 4;

    const float* Aptr = X + (size_t)(m0 + lrow) * K + lk;
    const float* Bptr = W + (size_t)(n0 + lrow) * K + lk;

    float acc[4][4] = {};
    for (int k0 = 0; k0 < K; k0 += BKK) {
        float4 a4 = *(const float4*)(Aptr + k0);
        float4 b4 = *(const float4*)(Bptr + k0);
        As[lk + 0][lrow] = a4.x; As[lk + 1][lrow] = a4.y;
        As[lk + 2][lrow] = a4.z; As[lk + 3][lrow] = a4.w;
        Bs[lk + 0][lrow] = b4.x; Bs[lk + 1][lrow] = b4.y;
        Bs[lk + 2][lrow] = b4.z; Bs[lk + 3][lrow] = b4.w;
        __syncthreads();
#pragma unroll
        for (int kk = 0; kk < BKK; kk++) {
            float4 av = *(const float4*)&As[kk][ty * 4];
            float4 bv = *(const float4*)&Bs[kk][tx * 4];
            float a[4] = {av.x, av.y, av.z, av.w};
            float b[4] = {bv.x, bv.y, bv.z, bv.w};
#pragma unroll
            for (int i = 0; i < 4; i++)
#pragma unroll
                for (int j = 0; j < 4; j++) acc[i][j] += a[i] * b[j];
        }
        __syncthreads();
    }

#pragma unroll
    for (int i = 0; i < 4; i++) {
        int m = m0 + ty * 4 + i;
#pragma unroll
        for (int j = 0; j < 4; j++) {
            int jj = n0 + tx * 4 + j;
            Out[(size_t)m * DMODEL + jj] = acc[i][j] + bias[jj];
        }
    }
}

extern "C" void kernel_launch(void* const* d_in, const int* in_sizes, int n_in,
                              void* d_out, int out_size)
{
    const float* q       = (const float*)d_in[0];
    const float* k       = (const float*)d_in[1];
    const float* v       = (const float*)d_in[2];
    const float* pos_emb = (const float*)d_in[3];
    const int*   mask    = (const int*)d_in[4];   // bool -> int32 in harness
    const float* Wq   = (const float*)d_in[5];
    const float* bq   = (const float*)d_in[6];
    const float* Wk   = (const float*)d_in[7];
    const float* bk   = (const float*)d_in[8];
    const float* Wv   = (const float*)d_in[9];
    const float* bv   = (const float*)d_in[10];
    const float* Wpos = (const float*)d_in[11];
    const float* Wout = (const float*)d_in[12];
    const float* bout = (const float*)d_in[13];
    const float* u      = (const float*)d_in[14];
    const float* v_bias = (const float*)d_in[15];

    float* out = (float*)d_out;
    float* out_ctx  = out;                                  // [8,1024,512]
    float* out_attn = out + (size_t)BATCH * SEQ * DMODEL;   // [8,8,1024,1024]

    static float *p_qu = nullptr, *p_qvb, *p_kh, *p_vh, *p_ph, *p_ctx, *p_pos;
    if (!p_qu) {
        cudaGetSymbolAddress((void**)&p_qu,  g_qu);
        cudaGetSymbolAddress((void**)&p_qvb, g_qvb);
        cudaGetSymbolAddress((void**)&p_kh,  g_kh);
        cudaGetSymbolAddress((void**)&p_vh,  g_vh);
        cudaGetSymbolAddress((void**)&p_ph,  g_ph);
        cudaGetSymbolAddress((void**)&p_ctx, g_ctx);
        cudaGetSymbolAddress((void**)&p_pos, g_pos);
    }

    dim3 gp(DMODEL / BN, (BATCH * SEQ) / BM);   // (8, 128)
    k_proj<<<gp, 256>>>(q,       Wq,   bq,      p_qu, u, p_qvb, v_bias);
    k_proj<<<gp, 256>>>(k,       Wk,   bk,      p_kh, nullptr, nullptr, nullptr);
    k_proj<<<gp, 256>>>(v,       Wv,   bv,      p_vh, nullptr, nullptr, nullptr);
    k_proj<<<gp, 256>>>(pos_emb, Wpos, nullptr, p_ph, nullptr, nullptr, nullptr);

    dim3 gs(SEQ / BN, SEQ / BM, 2 * BATCH * NHEAD); // (16, 16, 128)
    k_scores<<<gs, 256>>>(p_qu,  p_kh, out_attn,    // content -> d_out attn region
                          p_qvb, p_ph, p_pos);      // pos (pre-shift) -> scratch

    k_softmax<<<BATCH * NHEAD * SEQ, 256>>>(out_attn, p_pos, mask);

    dim3 ga(1, SEQ / BM, BATCH * NHEAD);        // (1, 16, 64)
    k_av<<<ga, 256>>>(out_attn, p_vh, p_ctx);

    k_out<<<gp, 256>>>(p_ctx, Wout, bout, out_ctx);
}

// round 5
// speedup vs baseline: 1.5902x; 1.5902x over previous
#include <cuda_runtime.h>
#include <cstdint>

#define BATCH 8
#define SEQ   1024
#define DMODEL 512
#define NHEAD 8
#define HDIM  64

#define BM 64
#define BN 64
#define BKK 16

// tf32 tensor-core tile config
#define TCPAD 68              // smem row stride in words (128 rows x 68)
#define TC_SMEM_BYTES (2 * 128 * TCPAD * 4)

static __device__ float g_qu [(size_t)BATCH*NHEAD*SEQ*HDIM];
static __device__ float g_qvb[(size_t)BATCH*NHEAD*SEQ*HDIM];
static __device__ float g_kh [(size_t)BATCH*NHEAD*SEQ*HDIM];
static __device__ float g_vh [(size_t)BATCH*NHEAD*SEQ*HDIM];
static __device__ float g_ph [(size_t)BATCH*NHEAD*SEQ*HDIM];
static __device__ float g_ctx[(size_t)BATCH*SEQ*DMODEL];
static __device__ float g_pos[(size_t)BATCH*NHEAD*SEQ*SEQ];

__device__ __forceinline__ uint32_t f2tf32(float x) {
    uint32_t t;
    asm("cvt.rna.tf32.f32 %0, %1;" : "=r"(t) : "f"(x));
    return t;
}

__device__ __forceinline__ void mma_tf32(float c[4], const uint32_t a[4], const uint32_t b[2]) {
    asm volatile(
        "mma.sync.aligned.m16n8k8.row.col.f32.tf32.tf32.f32 "
        "{%0,%1,%2,%3}, {%4,%5,%6,%7}, {%8,%9}, {%0,%1,%2,%3};"
        : "+f"(c[0]), "+f"(c[1]), "+f"(c[2]), "+f"(c[3])
        : "r"(a[0]), "r"(a[1]), "r"(a[2]), "r"(a[3]), "r"(b[0]), "r"(b[1]));
}

// ---------------------------------------------------------------------------
// TF32 NT projection GEMM: Y[m,j] = sum_d X[m,d]*W[j,d] (+ bias[j])
// 128x128 block tile, K=512 in 8 tiles of 64. Output scattered head-major,
// optional dual output (q projection: +u and +v_bias).
// ---------------------------------------------------------------------------
__global__ __launch_bounds__(256)
void k_proj_tc(const float* __restrict__ X, const float* __restrict__ W,
               const float* __restrict__ bias,
               float* __restrict__ O1, const float* __restrict__ add1,
               float* __restrict__ O2, const float* __restrict__ add2)
{
    extern __shared__ uint32_t sm[];
    uint32_t* As = sm;                 // [128][TCPAD]
    uint32_t* Bs = sm + 128 * TCPAD;   // [128][TCPAD]

    const int tid = threadIdx.x;
    const int m0 = blockIdx.y * 128;
    const int n0 = blockIdx.x * 128;
    const int lane = tid & 31, warp = tid >> 5;
    const int wm = (warp & 1) * 64, wn = (warp >> 1) * 32;
    const int grp = lane >> 2, tig = lane & 3;

    const int lrow  = tid >> 4;        // 0..15
    const int lcol4 = (tid & 15) * 4;  // 0..60

    float acc[4][4][4] = {};

    for (int k0 = 0; k0 < DMODEL; k0 += 64) {
#pragma unroll
        for (int i = 0; i < 8; i++) {
            int r = lrow + i * 16;
            float4 a4 = *(const float4*)(X + (size_t)(m0 + r) * DMODEL + k0 + lcol4);
            float4 b4 = *(const float4*)(W + (size_t)(n0 + r) * DMODEL + k0 + lcol4);
            *(uint4*)&As[r * TCPAD + lcol4] =
                make_uint4(f2tf32(a4.x), f2tf32(a4.y), f2tf32(a4.z), f2tf32(a4.w));
            *(uint4*)&Bs[r * TCPAD + lcol4] =
                make_uint4(f2tf32(b4.x), f2tf32(b4.y), f2tf32(b4.z), f2tf32(b4.w));
        }
        __syncthreads();

#pragma unroll
        for (int ks = 0; ks < 8; ks++) {
            const int kk = ks * 8;
            uint32_t a[4][4], b[4][2];
#pragma unroll
            for (int tm = 0; tm < 4; tm++) {
                int r = wm + tm * 16 + grp;
                a[tm][0] = As[r * TCPAD + kk + tig];
                a[tm][1] = As[(r + 8) * TCPAD + kk + tig];
                a[tm][2] = As[r * TCPAD + kk + tig + 4];
                a[tm][3] = As[(r + 8) * TCPAD + kk + tig + 4];
            }
#pragma unroll
            for (int tn = 0; tn < 4; tn++) {
                int c = wn + tn * 8 + grp;
                b[tn][0] = Bs[c * TCPAD + kk + tig];
                b[tn][1] = Bs[c * TCPAD + kk + tig + 4];
            }
#pragma unroll
            for (int tm = 0; tm < 4; tm++)
#pragma unroll
                for (int tn = 0; tn < 4; tn++)
                    mma_tf32(acc[tm][tn], a[tm], b[tn]);
        }
        __syncthreads();
    }

    // Epilogue: scatter to head-major [b][n][s][hd]
#pragma unroll
    for (int tm = 0; tm < 4; tm++) {
#pragma unroll
        for (int tn = 0; tn < 4; tn++) {
            int j = n0 + wn + tn * 8 + tig * 2;
            int hn = j >> 6, hd = j & (HDIM - 1);
            float bj0 = bias ? bias[j] : 0.0f;
            float bj1 = bias ? bias[j + 1] : 0.0f;
#pragma unroll
            for (int half = 0; half < 2; half++) {
                int m = m0 + wm + tm * 16 + grp + half * 8;
                int bb = m >> 10, s = m & (SEQ - 1);
                float v0 = acc[tm][tn][half * 2 + 0] + bj0;
                float v1 = acc[tm][tn][half * 2 + 1] + bj1;
                size_t off = (((size_t)bb * NHEAD + hn) * SEQ + s) * HDIM + hd;
                if (add1) {
                    *(float2*)&O1[off] = make_float2(v0 + add1[j], v1 + add1[j + 1]);
                } else {
                    *(float2*)&O1[off] = make_float2(v0, v1);
                }
                if (O2) {
                    *(float2*)&O2[off] = make_float2(v0 + add2[j], v1 + add2[j + 1]);
                }
            }
        }
    }
}

// ---------------------------------------------------------------------------
// TF32 batched score GEMM (NT, K=64): C[q,k] = sum_d A[q,d]*B[k,d]
// z in [0,64): content (qu x kh) -> C0 ; z in [64,128): pos (qvb x ph) -> C1
// 128x128 block tile, K=64 single smem tile.
// ---------------------------------------------------------------------------
__global__ __launch_bounds__(256)
void k_scores_tc(const float* __restrict__ A0, const float* __restrict__ B0,
                 float* __restrict__ C0,
                 const float* __restrict__ A1, const float* __restrict__ B1,
                 float* __restrict__ C1)
{
    extern __shared__ uint32_t sm[];
    uint32_t* As = sm;
    uint32_t* Bs = sm + 128 * TCPAD;

    int z = blockIdx.z;
    const float *Aall, *Ball; float* Call;
    if (z < BATCH * NHEAD) { Aall = A0; Ball = B0; Call = C0; }
    else { z -= BATCH * NHEAD; Aall = A1; Ball = B1; Call = C1; }
    const float* X = Aall + (size_t)z * SEQ * HDIM;
    const float* W = Ball + (size_t)z * SEQ * HDIM;
    float* C = Call + (size_t)z * SEQ * SEQ;

    const int tid = threadIdx.x;
    const int m0 = blockIdx.y * 128;
    const int n0 = blockIdx.x * 128;
    const int lane = tid & 31, warp = tid >> 5;
    const int wm = (warp & 1) * 64, wn = (warp >> 1) * 32;
    const int grp = lane >> 2, tig = lane & 3;

    const int lrow  = tid >> 4;
    const int lcol4 = (tid & 15) * 4;

#pragma unroll
    for (int i = 0; i < 8; i++) {
        int r = lrow + i * 16;
        float4 a4 = *(const float4*)(X + (size_t)(m0 + r) * HDIM + lcol4);
        float4 b4 = *(const float4*)(W + (size_t)(n0 + r) * HDIM + lcol4);
        *(uint4*)&As[r * TCPAD + lcol4] =
            make_uint4(f2tf32(a4.x), f2tf32(a4.y), f2tf32(a4.z), f2tf32(a4.w));
        *(uint4*)&Bs[r * TCPAD + lcol4] =
            make_uint4(f2tf32(b4.x), f2tf32(b4.y), f2tf32(b4.z), f2tf32(b4.w));
    }
    __syncthreads();

    float acc[4][4][4] = {};
#pragma unroll
    for (int ks = 0; ks < 8; ks++) {
        const int kk = ks * 8;
        uint32_t a[4][4], b[4][2];
#pragma unroll
        for (int tm = 0; tm < 4; tm++) {
            int r = wm + tm * 16 + grp;
            a[tm][0] = As[r * TCPAD + kk + tig];
            a[tm][1] = As[(r + 8) * TCPAD + kk + tig];
            a[tm][2] = As[r * TCPAD + kk + tig + 4];
            a[tm][3] = As[(r + 8) * TCPAD + kk + tig + 4];
        }
#pragma unroll
        for (int tn = 0; tn < 4; tn++) {
            int c = wn + tn * 8 + grp;
            b[tn][0] = Bs[c * TCPAD + kk + tig];
            b[tn][1] = Bs[c * TCPAD + kk + tig + 4];
        }
#pragma unroll
        for (int tm = 0; tm < 4; tm++)
#pragma unroll
            for (int tn = 0; tn < 4; tn++)
                mma_tf32(acc[tm][tn], a[tm], b[tn]);
    }

#pragma unroll
    for (int tm = 0; tm < 4; tm++) {
#pragma unroll
        for (int tn = 0; tn < 4; tn++) {
            int col = n0 + wn + tn * 8 + tig * 2;
#pragma unroll
            for (int half = 0; half < 2; half++) {
                int row = m0 + wm + tm * 16 + grp + half * 8;
                *(float2*)&C[(size_t)row * SEQ + col] =
                    make_float2(acc[tm][tn][half * 2 + 0], acc[tm][tn][half * 2 + 1]);
            }
        }
    }
}

// ---------------------------------------------------------------------------
// FP32 NT projection GEMM (kept for v: precision-critical path)
// ---------------------------------------------------------------------------
__global__ __launch_bounds__(256)
void k_proj(const float* __restrict__ X, const float* __restrict__ W,
            const float* __restrict__ bias,
            float* __restrict__ O1)
{
    __shared__ float As[BKK][BM + 4];
    __shared__ float Bs[BKK][BN + 4];
    const int K = DMODEL;
    const int tid = threadIdx.x;
    const int m0 = blockIdx.y * BM;
    const int n0 = blockIdx.x * BN;
    const int tx = tid & 15, ty = tid >> 4;
    const int lrow = tid >> 2, lk = (tid & 3) * 4;

    const float* Aptr = X + (size_t)(m0 + lrow) * K + lk;
    const float* Bptr = W + (size_t)(n0 + lrow) * K + lk;

    float acc[4][4] = {};
    for (int k0 = 0; k0 < K; k0 += BKK) {
        float4 a4 = *(const float4*)(Aptr + k0);
        float4 b4 = *(const float4*)(Bptr + k0);
        As[lk + 0][lrow] = a4.x; As[lk + 1][lrow] = a4.y;
        As[lk + 2][lrow] = a4.z; As[lk + 3][lrow] = a4.w;
        Bs[lk + 0][lrow] = b4.x; Bs[lk + 1][lrow] = b4.y;
        Bs[lk + 2][lrow] = b4.z; Bs[lk + 3][lrow] = b4.w;
        __syncthreads();
#pragma unroll
        for (int kk = 0; kk < BKK; kk++) {
            float4 av = *(const float4*)&As[kk][ty * 4];
            float4 bv = *(const float4*)&Bs[kk][tx * 4];
            float a[4] = {av.x, av.y, av.z, av.w};
            float b[4] = {bv.x, bv.y, bv.z, bv.w};
#pragma unroll
            for (int i = 0; i < 4; i++)
#pragma unroll
                for (int j = 0; j < 4; j++) acc[i][j] += a[i] * b[j];
        }
        __syncthreads();
    }

#pragma unroll
    for (int i = 0; i < 4; i++) {
        int m = m0 + ty * 4 + i;
        int bb = m >> 10, s = m & (SEQ - 1);
#pragma unroll
        for (int j = 0; j < 4; j++) {
            int jj = n0 + tx * 4 + j;
            int n = jj >> 6, hd = jj & (HDIM - 1);
            size_t off = (((size_t)bb * NHEAD + n) * SEQ + s) * HDIM + hd;
            O1[off] = acc[i][j] + bias[jj];
        }
    }
}

// ---------------------------------------------------------------------------
// Fused relative shift + scale + mask + softmax. One block per (b,n,q) row.
// shift[q,k] = pos[q, S-1-q+k] (k<=q); 0 (k==q+1); pos[q+1, k-q-2] (k>q+1)
// ---------------------------------------------------------------------------
__global__ __launch_bounds__(256)
void k_softmax(float* __restrict__ AttnOut, const float* __restrict__ Pos,
               const int* __restrict__ Mask)
{
    const int row = blockIdx.x;
    const int q = row & (SEQ - 1);
    const int z = row >> 10;
    const int b = z >> 3;

    float* Crow = AttnOut + (size_t)row * SEQ;
    const float* P0 = Pos + ((size_t)z * SEQ + q) * SEQ;
    const float* P1 = Pos + ((size_t)z * SEQ + q + 1) * SEQ;
    const int* Mrow = Mask + ((size_t)b * SEQ + q) * SEQ;

    const float scale = 0.04419417382415922f;  // 1/sqrt(512)
    const int tid = threadIdx.x;

    float vals[4];
    float lmax = -3.0e38f;
#pragma unroll
    for (int i = 0; i < 4; i++) {
        int k = tid + i * 256;
        float c = Crow[k];
        float p;
        if (k <= q)           p = P0[SEQ - 1 - q + k];
        else if (k == q + 1)  p = 0.0f;
        else                  p = P1[k - q - 2];
        float sc = (c + p) * scale;
        if (Mrow[k] != 0) sc = -10000.0f;
        vals[i] = sc;
        lmax = fmaxf(lmax, sc);
    }

    __shared__ float red[8];
#pragma unroll
    for (int o = 16; o; o >>= 1) lmax = fmaxf(lmax, __shfl_xor_sync(0xffffffffu, lmax, o));
    if ((tid & 31) == 0) red[tid >> 5] = lmax;
    __syncthreads();
    float bmax = red[0];
#pragma unroll
    for (int w = 1; w < 8; w++) bmax = fmaxf(bmax, red[w]);

    float lsum = 0.0f;
#pragma unroll
    for (int i = 0; i < 4; i++) {
        vals[i] = __expf(vals[i] - bmax);
        lsum += vals[i];
    }
#pragma unroll
    for (int o = 16; o; o >>= 1) lsum += __shfl_xor_sync(0xffffffffu, lsum, o);
    __syncthreads();
    if ((tid & 31) == 0) red[tid >> 5] = lsum;
    __syncthreads();
    float tot = 0.0f;
#pragma unroll
    for (int w = 0; w < 8; w++) tot += red[w];
    float inv = 1.0f / tot;

#pragma unroll
    for (int i = 0; i < 4; i++) {
        int k = tid + i * 256;
        Crow[k] = vals[i] * inv;
    }
}

// ---------------------------------------------------------------------------
// Batched AV GEMM (NN, fp32): Ctx[b][q][n*HDIM+d] = sum_k attn[z][q][k]*vh[z][k][d]
// ---------------------------------------------------------------------------
__global__ __launch_bounds__(256)
void k_av(const float* __restrict__ Attn, const float* __restrict__ Vall,
          float* __restrict__ Ctx)
{
    __shared__ float As[BKK][BM + 4];
    __shared__ float Bs[BKK][BN];
    const int z = blockIdx.z;
    const int b = z >> 3, n = z & 7;
    const float* Ab = Attn + (size_t)z * SEQ * SEQ;
    const float* Bb = Vall + (size_t)z * SEQ * HDIM;

    const int tid = threadIdx.x;
    const int m0 = blockIdx.y * BM;
    const int tx = tid & 15, ty = tid >> 4;
    const int lrow = tid >> 2, lk = (tid & 3) * 4;
    const int brow = tid >> 4, bcol = (tid & 15) * 4;

    float acc[4][4] = {};
    for (int k0 = 0; k0 < SEQ; k0 += BKK) {
        float4 a4 = *(const float4*)(Ab + (size_t)(m0 + lrow) * SEQ + k0 + lk);
        As[lk + 0][lrow] = a4.x; As[lk + 1][lrow] = a4.y;
        As[lk + 2][lrow] = a4.z; As[lk + 3][lrow] = a4.w;
        float4 b4 = *(const float4*)(Bb + (size_t)(k0 + brow) * HDIM + bcol);
        *(float4*)&Bs[brow][bcol] = b4;
        __syncthreads();
#pragma unroll
        for (int kk = 0; kk < BKK; kk++) {
            float4 av = *(const float4*)&As[kk][ty * 4];
            float4 bv = *(const float4*)&Bs[kk][tx * 4];
            float a[4] = {av.x, av.y, av.z, av.w};
            float bvv[4] = {bv.x, bv.y, bv.z, bv.w};
#pragma unroll
            for (int i = 0; i < 4; i++)
#pragma unroll
                for (int j = 0; j < 4; j++) acc[i][j] += a[i] * bvv[j];
        }
        __syncthreads();
    }

#pragma unroll
    for (int i = 0; i < 4; i++) {
        int qrow = m0 + ty * 4 + i;
#pragma unroll
        for (int j = 0; j < 4; j++) {
            int d = tx * 4 + j;
            Ctx[((size_t)b * SEQ + qrow) * DMODEL + n * HDIM + d] = acc[i][j];
        }
    }
}

// ---------------------------------------------------------------------------
// Output NT GEMM (fp32): Out[m,j] = sum_d Ctx[m,d]*Wout[j,d] + bout[j]
// ---------------------------------------------------------------------------
__global__ __launch_bounds__(256)
void k_out(const float* __restrict__ X, const float* __restrict__ W,
           const float* __restrict__ bias, float* __restrict__ Out)
{
    __shared__ float As[BKK][BM + 4];
    __shared__ float Bs[BKK][BN + 4];
    const int K = DMODEL;
    const int tid = threadIdx.x;
    const int m0 = blockIdx.y * BM;
    const int n0 = blockIdx.x * BN;
    const int tx = tid & 15, ty = tid >> 4;
    const int lrow = tid >> 2, lk = (tid & 3) * 4;

    const float* Aptr = X + (size_t)(m0 + lrow) * K + lk;
    const float* Bptr = W + (size_t)(n0 + lrow) * K + lk;

    float acc[4][4] = {};
    for (int k0 = 0; k0 < K; k0 += BKK) {
        float4 a4 = *(const float4*)(Aptr + k0);
        float4 b4 = *(const float4*)(Bptr + k0);
        As[lk + 0][lrow] = a4.x; As[lk + 1][lrow] = a4.y;
        As[lk + 2][lrow] = a4.z; As[lk + 3][lrow] = a4.w;
        Bs[lk + 0][lrow] = b4.x; Bs[lk + 1][lrow] = b4.y;
        Bs[lk + 2][lrow] = b4.z; Bs[lk + 3][lrow] = b4.w;
        __syncthreads();
#pragma unroll
        for (int kk = 0; kk < BKK; kk++) {
            float4 av = *(const float4*)&As[kk][ty * 4];
            float4 bv = *(const float4*)&Bs[kk][tx * 4];
            float a[4] = {av.x, av.y, av.z, av.w};
            float b[4] = {bv.x, bv.y, bv.z, bv.w};
#pragma unroll
            for (int i = 0; i < 4; i++)
#pragma unroll
                for (int j = 0; j < 4; j++) acc[i][j] += a[i] * b[j];
        }
        __syncthreads();
    }

#pragma unroll
    for (int i = 0; i < 4; i++) {
        int m = m0 + ty * 4 + i;
#pragma unroll
        for (int j = 0; j < 4; j++) {
            int jj = n0 + tx * 4 + j;
            Out[(size_t)m * DMODEL + jj] = acc[i][j] + bias[jj];
        }
    }
}

extern "C" void kernel_launch(void* const* d_in, const int* in_sizes, int n_in,
                              void* d_out, int out_size)
{
    const float* q       = (const float*)d_in[0];
    const float* k       = (const float*)d_in[1];
    const float* v       = (const float*)d_in[2];
    const float* pos_emb = (const float*)d_in[3];
    const int*   mask    = (const int*)d_in[4];   // bool -> int32 in harness
    const float* Wq   = (const float*)d_in[5];
    const float* bq   = (const float*)d_in[6];
    const float* Wk   = (const float*)d_in[7];
    const float* bk   = (const float*)d_in[8];
    const float* Wv   = (const float*)d_in[9];
    const float* bv   = (const float*)d_in[10];
    const float* Wpos = (const float*)d_in[11];
    const float* Wout = (const float*)d_in[12];
    const float* bout = (const float*)d_in[13];
    const float* u      = (const float*)d_in[14];
    const float* v_bias = (const float*)d_in[15];

    float* out = (float*)d_out;
    float* out_ctx  = out;                                  // [8,1024,512]
    float* out_attn = out + (size_t)BATCH * SEQ * DMODEL;   // [8,8,1024,1024]

    static float *p_qu = nullptr, *p_qvb, *p_kh, *p_vh, *p_ph, *p_ctx, *p_pos;
    if (!p_qu) {
        cudaGetSymbolAddress((void**)&p_qu,  g_qu);
        cudaGetSymbolAddress((void**)&p_qvb, g_qvb);
        cudaGetSymbolAddress((void**)&p_kh,  g_kh);
        cudaGetSymbolAddress((void**)&p_vh,  g_vh);
        cudaGetSymbolAddress((void**)&p_ph,  g_ph);
        cudaGetSymbolAddress((void**)&p_ctx, g_ctx);
        cudaGetSymbolAddress((void**)&p_pos, g_pos);
        cudaFuncSetAttribute(k_proj_tc,   cudaFuncAttributeMaxDynamicSharedMemorySize, TC_SMEM_BYTES);
        cudaFuncSetAttribute(k_scores_tc, cudaFuncAttributeMaxDynamicSharedMemorySize, TC_SMEM_BYTES);
    }

    // tf32 tensor projections (q/k/pos -> feed score path, error attenuated by softmax)
    dim3 gptc(DMODEL / 128, (BATCH * SEQ) / 128);   // (4, 64)
    k_proj_tc<<<gptc, 256, TC_SMEM_BYTES>>>(q,       Wq,   bq, p_qu, u, p_qvb, v_bias);
    k_proj_tc<<<gptc, 256, TC_SMEM_BYTES>>>(k,       Wk,   bk, p_kh, nullptr, nullptr, nullptr);
    k_proj_tc<<<gptc, 256, TC_SMEM_BYTES>>>(pos_emb, Wpos, nullptr, p_ph, nullptr, nullptr, nullptr);

    // fp32 projection for v (precision-critical: feeds context directly)
    dim3 gp(DMODEL / BN, (BATCH * SEQ) / BM);       // (8, 128)
    k_proj<<<gp, 256>>>(v, Wv, bv, p_vh);

    // tf32 tensor score GEMMs (both content and pos in one launch)
    dim3 gs(SEQ / 128, SEQ / 128, 2 * BATCH * NHEAD); // (8, 8, 128)
    k_scores_tc<<<gs, 256, TC_SMEM_BYTES>>>(p_qu,  p_kh, out_attn,
                                            p_qvb, p_ph, p_pos);

    k_softmax<<<BATCH * NHEAD * SEQ, 256>>>(out_attn, p_pos, mask);

    dim3 ga(1, SEQ / BM, BATCH * NHEAD);            // (1, 16, 64)
    k_av<<<ga, 256>>>(out_attn, p_vh, p_ctx);

    k_out<<<gp, 256>>>(p_ctx, Wout, bout, out_ctx);
}

// round 6
// speedup vs baseline: 2.1627x; 1.3600x over previous
#include <cuda_runtime.h>
#include <cstdint>

#define BATCH 8
#define SEQ   1024
#define DMODEL 512
#define NHEAD 8
#define HDIM  64

// tf32 tensor-core tile config
#define TCPAD 68              // smem row stride in words
#define TC_SMEM_BYTES (2 * 128 * TCPAD * 4)
#define AV_SMEM_BYTES ((128 * TCPAD + 64 * TCPAD) * 4)

static __device__ float g_qu [(size_t)BATCH*NHEAD*SEQ*HDIM];
static __device__ float g_qvb[(size_t)BATCH*NHEAD*SEQ*HDIM];
static __device__ float g_kh [(size_t)BATCH*NHEAD*SEQ*HDIM];
static __device__ float g_vh [(size_t)BATCH*NHEAD*SEQ*HDIM];
static __device__ float g_ph [(size_t)BATCH*NHEAD*SEQ*HDIM];
static __device__ float g_ctx[(size_t)BATCH*SEQ*DMODEL];
static __device__ float g_pos[(size_t)BATCH*NHEAD*SEQ*SEQ];

__device__ __forceinline__ uint32_t f2tf32(float x) {
    uint32_t t;
    asm("cvt.rna.tf32.f32 %0, %1;" : "=r"(t) : "f"(x));
    return t;
}

__device__ __forceinline__ void mma_tf32(float c[4], const uint32_t a[4], const uint32_t b[2]) {
    asm volatile(
        "mma.sync.aligned.m16n8k8.row.col.f32.tf32.tf32.f32 "
        "{%0,%1,%2,%3}, {%4,%5,%6,%7}, {%8,%9}, {%0,%1,%2,%3};"
        : "+f"(c[0]), "+f"(c[1]), "+f"(c[2]), "+f"(c[3])
        : "r"(a[0]), "r"(a[1]), "r"(a[2]), "r"(a[3]), "r"(b[0]), "r"(b[1]));
}

// ---------------------------------------------------------------------------
// TF32 NT projection GEMM: Y[m,j] = sum_d X[m,d]*W[j,d] (+ bias[j])
// 128x128 block tile. Output scattered head-major, optional dual output.
// ---------------------------------------------------------------------------
__global__ __launch_bounds__(256)
void k_proj_tc(const float* __restrict__ X, const float* __restrict__ W,
               const float* __restrict__ bias,
               float* __restrict__ O1, const float* __restrict__ add1,
               float* __restrict__ O2, const float* __restrict__ add2)
{
    extern __shared__ uint32_t sm[];
    uint32_t* As = sm;                 // [128][TCPAD]
    uint32_t* Bs = sm + 128 * TCPAD;   // [128][TCPAD]

    const int tid = threadIdx.x;
    const int m0 = blockIdx.y * 128;
    const int n0 = blockIdx.x * 128;
    const int lane = tid & 31, warp = tid >> 5;
    const int wm = (warp & 1) * 64, wn = (warp >> 1) * 32;
    const int grp = lane >> 2, tig = lane & 3;

    const int lrow  = tid >> 4;        // 0..15
    const int lcol4 = (tid & 15) * 4;  // 0..60

    float acc[4][4][4] = {};

    for (int k0 = 0; k0 < DMODEL; k0 += 64) {
#pragma unroll
        for (int i = 0; i < 8; i++) {
            int r = lrow + i * 16;
            float4 a4 = *(const float4*)(X + (size_t)(m0 + r) * DMODEL + k0 + lcol4);
            float4 b4 = *(const float4*)(W + (size_t)(n0 + r) * DMODEL + k0 + lcol4);
            *(uint4*)&As[r * TCPAD + lcol4] =
                make_uint4(f2tf32(a4.x), f2tf32(a4.y), f2tf32(a4.z), f2tf32(a4.w));
            *(uint4*)&Bs[r * TCPAD + lcol4] =
                make_uint4(f2tf32(b4.x), f2tf32(b4.y), f2tf32(b4.z), f2tf32(b4.w));
        }
        __syncthreads();

#pragma unroll
        for (int ks = 0; ks < 8; ks++) {
            const int kk = ks * 8;
            uint32_t a[4][4], b[4][2];
#pragma unroll
            for (int tm = 0; tm < 4; tm++) {
                int r = wm + tm * 16 + grp;
                a[tm][0] = As[r * TCPAD + kk + tig];
                a[tm][1] = As[(r + 8) * TCPAD + kk + tig];
                a[tm][2] = As[r * TCPAD + kk + tig + 4];
                a[tm][3] = As[(r + 8) * TCPAD + kk + tig + 4];
            }
#pragma unroll
            for (int tn = 0; tn < 4; tn++) {
                int c = wn + tn * 8 + grp;
                b[tn][0] = Bs[c * TCPAD + kk + tig];
                b[tn][1] = Bs[c * TCPAD + kk + tig + 4];
            }
#pragma unroll
            for (int tm = 0; tm < 4; tm++)
#pragma unroll
                for (int tn = 0; tn < 4; tn++)
                    mma_tf32(acc[tm][tn], a[tm], b[tn]);
        }
        __syncthreads();
    }

    // Epilogue: scatter to head-major [b][n][s][hd]
#pragma unroll
    for (int tm = 0; tm < 4; tm++) {
#pragma unroll
        for (int tn = 0; tn < 4; tn++) {
            int j = n0 + wn + tn * 8 + tig * 2;
            int hn = j >> 6, hd = j & (HDIM - 1);
            float bj0 = bias ? bias[j] : 0.0f;
            float bj1 = bias ? bias[j + 1] : 0.0f;
#pragma unroll
            for (int half = 0; half < 2; half++) {
                int m = m0 + wm + tm * 16 + grp + half * 8;
                int bb = m >> 10, s = m & (SEQ - 1);
                float v0 = acc[tm][tn][half * 2 + 0] + bj0;
                float v1 = acc[tm][tn][half * 2 + 1] + bj1;
                size_t off = (((size_t)bb * NHEAD + hn) * SEQ + s) * HDIM + hd;
                if (add1) {
                    *(float2*)&O1[off] = make_float2(v0 + add1[j], v1 + add1[j + 1]);
                } else {
                    *(float2*)&O1[off] = make_float2(v0, v1);
                }
                if (O2) {
                    *(float2*)&O2[off] = make_float2(v0 + add2[j], v1 + add2[j + 1]);
                }
            }
        }
    }
}

// ---------------------------------------------------------------------------
// TF32 batched score GEMM (NT, K=64): C[q,k] = sum_d A[q,d]*B[k,d]
// z in [0,64): content (qu x kh) -> C0 ; z in [64,128): pos (qvb x ph) -> C1
// ---------------------------------------------------------------------------
__global__ __launch_bounds__(256)
void k_scores_tc(const float* __restrict__ A0, const float* __restrict__ B0,
                 float* __restrict__ C0,
                 const float* __restrict__ A1, const float* __restrict__ B1,
                 float* __restrict__ C1)
{
    extern __shared__ uint32_t sm[];
    uint32_t* As = sm;
    uint32_t* Bs = sm + 128 * TCPAD;

    int z = blockIdx.z;
    const float *Aall, *Ball; float* Call;
    if (z < BATCH * NHEAD) { Aall = A0; Ball = B0; Call = C0; }
    else { z -= BATCH * NHEAD; Aall = A1; Ball = B1; Call = C1; }
    const float* X = Aall + (size_t)z * SEQ * HDIM;
    const float* W = Ball + (size_t)z * SEQ * HDIM;
    float* C = Call + (size_t)z * SEQ * SEQ;

    const int tid = threadIdx.x;
    const int m0 = blockIdx.y * 128;
    const int n0 = blockIdx.x * 128;
    const int lane = tid & 31, warp = tid >> 5;
    const int wm = (warp & 1) * 64, wn = (warp >> 1) * 32;
    const int grp = lane >> 2, tig = lane & 3;

    const int lrow  = tid >> 4;
    const int lcol4 = (tid & 15) * 4;

#pragma unroll
    for (int i = 0; i < 8; i++) {
        int r = lrow + i * 16;
        float4 a4 = *(const float4*)(X + (size_t)(m0 + r) * HDIM + lcol4);
        float4 b4 = *(const float4*)(W + (size_t)(n0 + r) * HDIM + lcol4);
        *(uint4*)&As[r * TCPAD + lcol4] =
            make_uint4(f2tf32(a4.x), f2tf32(a4.y), f2tf32(a4.z), f2tf32(a4.w));
        *(uint4*)&Bs[r * TCPAD + lcol4] =
            make_uint4(f2tf32(b4.x), f2tf32(b4.y), f2tf32(b4.z), f2tf32(b4.w));
    }
    __syncthreads();

    float acc[4][4][4] = {};
#pragma unroll
    for (int ks = 0; ks < 8; ks++) {
        const int kk = ks * 8;
        uint32_t a[4][4], b[4][2];
#pragma unroll
        for (int tm = 0; tm < 4; tm++) {
            int r = wm + tm * 16 + grp;
            a[tm][0] = As[r * TCPAD + kk + tig];
            a[tm][1] = As[(r + 8) * TCPAD + kk + tig];
            a[tm][2] = As[r * TCPAD + kk + tig + 4];
            a[tm][3] = As[(r + 8) * TCPAD + kk + tig + 4];
        }
#pragma unroll
        for (int tn = 0; tn < 4; tn++) {
            int c = wn + tn * 8 + grp;
            b[tn][0] = Bs[c * TCPAD + kk + tig];
            b[tn][1] = Bs[c * TCPAD + kk + tig + 4];
        }
#pragma unroll
        for (int tm = 0; tm < 4; tm++)
#pragma unroll
            for (int tn = 0; tn < 4; tn++)
                mma_tf32(acc[tm][tn], a[tm], b[tn]);
    }

#pragma unroll
    for (int tm = 0; tm < 4; tm++) {
#pragma unroll
        for (int tn = 0; tn < 4; tn++) {
            int col = n0 + wn + tn * 8 + tig * 2;
#pragma unroll
            for (int half = 0; half < 2; half++) {
                int row = m0 + wm + tm * 16 + grp + half * 8;
                *(float2*)&C[(size_t)row * SEQ + col] =
                    make_float2(acc[tm][tn][half * 2 + 0], acc[tm][tn][half * 2 + 1]);
            }
        }
    }
}

// ---------------------------------------------------------------------------
// TF32 batched AV GEMM (NN): Ctx[b][q][n*HDIM+d] = sum_k attn[z][q][k]*vh[z][k][d]
// 128x64 block tile, K=1024 streamed in 64-chunks. B kept [k][d] in smem;
// B-fragment gathered row-wise (2-way LDS conflicts, no transposed stores).
// ---------------------------------------------------------------------------
__global__ __launch_bounds__(256)
void k_av_tc(const float* __restrict__ Attn, const float* __restrict__ Vall,
             float* __restrict__ Ctx)
{
    extern __shared__ uint32_t sm[];
    uint32_t* As = sm;               // [128][TCPAD]
    uint32_t* Bs = sm + 128 * TCPAD; // [64][TCPAD]

    const int z = blockIdx.z;
    const int b = z >> 3, n = z & 7;
    const float* Ab = Attn + (size_t)z * SEQ * SEQ;
    const float* Bb = Vall + (size_t)z * SEQ * HDIM;

    const int tid = threadIdx.x;
    const int m0 = blockIdx.y * 128;
    const int lane = tid & 31, warp = tid >> 5;
    const int wm = (warp & 3) * 32, wn = (warp >> 2) * 32;  // 4x2 warp grid, 32x32 tiles
    const int grp = lane >> 2, tig = lane & 3;

    const int lrow  = tid >> 4;        // 0..15
    const int lcol4 = (tid & 15) * 4;  // 0..60

    float acc[2][4][4] = {};

    for (int k0 = 0; k0 < SEQ; k0 += 64) {
#pragma unroll
        for (int i = 0; i < 8; i++) {
            int r = lrow + i * 16;
            float4 a4 = *(const float4*)(Ab + (size_t)(m0 + r) * SEQ + k0 + lcol4);
            *(uint4*)&As[r * TCPAD + lcol4] =
                make_uint4(f2tf32(a4.x), f2tf32(a4.y), f2tf32(a4.z), f2tf32(a4.w));
        }
#pragma unroll
        for (int i = 0; i < 4; i++) {
            int r = lrow + i * 16;   // k-row within chunk
            float4 b4 = *(const float4*)(Bb + (size_t)(k0 + r) * HDIM + lcol4);
            *(uint4*)&Bs[r * TCPAD + lcol4] =
                make_uint4(f2tf32(b4.x), f2tf32(b4.y), f2tf32(b4.z), f2tf32(b4.w));
        }
        __syncthreads();

#pragma unroll
        for (int ks = 0; ks < 8; ks++) {
            const int kk = ks * 8;
            uint32_t a[2][4], bfr[4][2];
#pragma unroll
            for (int tm = 0; tm < 2; tm++) {
                int r = wm + tm * 16 + grp;
                a[tm][0] = As[r * TCPAD + kk + tig];
                a[tm][1] = As[(r + 8) * TCPAD + kk + tig];
                a[tm][2] = As[r * TCPAD + kk + tig + 4];
                a[tm][3] = As[(r + 8) * TCPAD + kk + tig + 4];
            }
#pragma unroll
            for (int tn = 0; tn < 4; tn++) {
                int c = wn + tn * 8 + grp;          // output column d
                bfr[tn][0] = Bs[(kk + tig) * TCPAD + c];
                bfr[tn][1] = Bs[(kk + tig + 4) * TCPAD + c];
            }
#pragma unroll
            for (int tm = 0; tm < 2; tm++)
#pragma unroll
                for (int tn = 0; tn < 4; tn++)
                    mma_tf32(acc[tm][tn], a[tm], bfr[tn]);
        }
        __syncthreads();
    }

#pragma unroll
    for (int tm = 0; tm < 2; tm++) {
#pragma unroll
        for (int tn = 0; tn < 4; tn++) {
            int d = wn + tn * 8 + tig * 2;
#pragma unroll
            for (int half = 0; half < 2; half++) {
                int qrow = m0 + wm + tm * 16 + grp + half * 8;
                *(float2*)&Ctx[((size_t)b * SEQ + qrow) * DMODEL + n * HDIM + d] =
                    make_float2(acc[tm][tn][half * 2 + 0], acc[tm][tn][half * 2 + 1]);
            }
        }
    }
}

// ---------------------------------------------------------------------------
// TF32 output NT GEMM: Out[m,j] = sum_d Ctx[m,d]*Wout[j,d] + bout[j] (row-major)
// ---------------------------------------------------------------------------
__global__ __launch_bounds__(256)
void k_out_tc(const float* __restrict__ X, const float* __restrict__ W,
              const float* __restrict__ bias, float* __restrict__ Out)
{
    extern __shared__ uint32_t sm[];
    uint32_t* As = sm;
    uint32_t* Bs = sm + 128 * TCPAD;

    const int tid = threadIdx.x;
    const int m0 = blockIdx.y * 128;
    const int n0 = blockIdx.x * 128;
    const int lane = tid & 31, warp = tid >> 5;
    const int wm = (warp & 1) * 64, wn = (warp >> 1) * 32;
    const int grp = lane >> 2, tig = lane & 3;

    const int lrow  = tid >> 4;
    const int lcol4 = (tid & 15) * 4;

    float acc[4][4][4] = {};

    for (int k0 = 0; k0 < DMODEL; k0 += 64) {
#pragma unroll
        for (int i = 0; i < 8; i++) {
            int r = lrow + i * 16;
            float4 a4 = *(const float4*)(X + (size_t)(m0 + r) * DMODEL + k0 + lcol4);
            float4 b4 = *(const float4*)(W + (size_t)(n0 + r) * DMODEL + k0 + lcol4);
            *(uint4*)&As[r * TCPAD + lcol4] =
                make_uint4(f2tf32(a4.x), f2tf32(a4.y), f2tf32(a4.z), f2tf32(a4.w));
            *(uint4*)&Bs[r * TCPAD + lcol4] =
                make_uint4(f2tf32(b4.x), f2tf32(b4.y), f2tf32(b4.z), f2tf32(b4.w));
        }
        __syncthreads();

#pragma unroll
        for (int ks = 0; ks < 8; ks++) {
            const int kk = ks * 8;
            uint32_t a[4][4], b[4][2];
#pragma unroll
            for (int tm = 0; tm < 4; tm++) {
                int r = wm + tm * 16 + grp;
                a[tm][0] = As[r * TCPAD + kk + tig];
                a[tm][1] = As[(r + 8) * TCPAD + kk + tig];
                a[tm][2] = As[r * TCPAD + kk + tig + 4];
                a[tm][3] = As[(r + 8) * TCPAD + kk + tig + 4];
            }
#pragma unroll
            for (int tn = 0; tn < 4; tn++) {
                int c = wn + tn * 8 + grp;
                b[tn][0] = Bs[c * TCPAD + kk + tig];
                b[tn][1] = Bs[c * TCPAD + kk + tig + 4];
            }
#pragma unroll
            for (int tm = 0; tm < 4; tm++)
#pragma unroll
                for (int tn = 0; tn < 4; tn++)
                    mma_tf32(acc[tm][tn], a[tm], b[tn]);
        }
        __syncthreads();
    }

#pragma unroll
    for (int tm = 0; tm < 4; tm++) {
#pragma unroll
        for (int tn = 0; tn < 4; tn++) {
            int j = n0 + wn + tn * 8 + tig * 2;
            float bj0 = bias[j], bj1 = bias[j + 1];
#pragma unroll
            for (int half = 0; half < 2; half++) {
                int m = m0 + wm + tm * 16 + grp + half * 8;
                *(float2*)&Out[(size_t)m * DMODEL + j] =
                    make_float2(acc[tm][tn][half * 2 + 0] + bj0,
                                acc[tm][tn][half * 2 + 1] + bj1);
            }
        }
    }
}

// ---------------------------------------------------------------------------
// Fused relative shift + scale + mask + softmax. One block per (b,n,q) row.
// shift[q,k] = pos[q, S-1-q+k] (k<=q); 0 (k==q+1); pos[q+1, k-q-2] (k>q+1)
// ---------------------------------------------------------------------------
__global__ __launch_bounds__(256)
void k_softmax(float* __restrict__ AttnOut, const float* __restrict__ Pos,
               const int* __restrict__ Mask)
{
    const int row = blockIdx.x;
    const int q = row & (SEQ - 1);
    const int z = row >> 10;
    const int b = z >> 3;

    float* Crow = AttnOut + (size_t)row * SEQ;
    const float* P0 = Pos + ((size_t)z * SEQ + q) * SEQ;
    const float* P1 = Pos + ((size_t)z * SEQ + q + 1) * SEQ;
    const int* Mrow = Mask + ((size_t)b * SEQ + q) * SEQ;

    const float scale = 0.04419417382415922f;  // 1/sqrt(512)
    const int tid = threadIdx.x;

    float vals[4];
    float lmax = -3.0e38f;
#pragma unroll
    for (int i = 0; i < 4; i++) {
        int k = tid + i * 256;
        float c = Crow[k];
        float p;
        if (k <= q)           p = P0[SEQ - 1 - q + k];
        else if (k == q + 1)  p = 0.0f;
        else                  p = P1[k - q - 2];
        float sc = (c + p) * scale;
        if (Mrow[k] != 0) sc = -10000.0f;
        vals[i] = sc;
        lmax = fmaxf(lmax, sc);
    }

    __shared__ float red[8];
#pragma unroll
    for (int o = 16; o; o >>= 1) lmax = fmaxf(lmax, __shfl_xor_sync(0xffffffffu, lmax, o));
    if ((tid & 31) == 0) red[tid >> 5] = lmax;
    __syncthreads();
    float bmax = red[0];
#pragma unroll
    for (int w = 1; w < 8; w++) bmax = fmaxf(bmax, red[w]);

    float lsum = 0.0f;
#pragma unroll
    for (int i = 0; i < 4; i++) {
        vals[i] = __expf(vals[i] - bmax);
        lsum += vals[i];
    }
#pragma unroll
    for (int o = 16; o; o >>= 1) lsum += __shfl_xor_sync(0xffffffffu, lsum, o);
    __syncthreads();
    if ((tid & 31) == 0) red[tid >> 5] = lsum;
    __syncthreads();
    float tot = 0.0f;
#pragma unroll
    for (int w = 0; w < 8; w++) tot += red[w];
    float inv = 1.0f / tot;

#pragma unroll
    for (int i = 0; i < 4; i++) {
        int k = tid + i * 256;
        Crow[k] = vals[i] * inv;
    }
}

extern "C" void kernel_launch(void* const* d_in, const int* in_sizes, int n_in,
                              void* d_out, int out_size)
{
    const float* q       = (const float*)d_in[0];
    const float* k       = (const float*)d_in[1];
    const float* v       = (const float*)d_in[2];
    const float* pos_emb = (const float*)d_in[3];
    const int*   mask    = (const int*)d_in[4];   // bool -> int32 in harness
    const float* Wq   = (const float*)d_in[5];
    const float* bq   = (const float*)d_in[6];
    const float* Wk   = (const float*)d_in[7];
    const float* bk   = (const float*)d_in[8];
    const float* Wv   = (const float*)d_in[9];
    const float* bv   = (const float*)d_in[10];
    const float* Wpos = (const float*)d_in[11];
    const float* Wout = (const float*)d_in[12];
    const float* bout = (const float*)d_in[13];
    const float* u      = (const float*)d_in[14];
    const float* v_bias = (const float*)d_in[15];

    float* out = (float*)d_out;
    float* out_ctx  = out;                                  // [8,1024,512]
    float* out_attn = out + (size_t)BATCH * SEQ * DMODEL;   // [8,8,1024,1024]

    static float *p_qu = nullptr, *p_qvb, *p_kh, *p_vh, *p_ph, *p_ctx, *p_pos;
    if (!p_qu) {
        cudaGetSymbolAddress((void**)&p_qu,  g_qu);
        cudaGetSymbolAddress((void**)&p_qvb, g_qvb);
        cudaGetSymbolAddress((void**)&p_kh,  g_kh);
        cudaGetSymbolAddress((void**)&p_vh,  g_vh);
        cudaGetSymbolAddress((void**)&p_ph,  g_ph);
        cudaGetSymbolAddress((void**)&p_ctx, g_ctx);
        cudaGetSymbolAddress((void**)&p_pos, g_pos);
        cudaFuncSetAttribute(k_proj_tc,   cudaFuncAttributeMaxDynamicSharedMemorySize, TC_SMEM_BYTES);
        cudaFuncSetAttribute(k_scores_tc, cudaFuncAttributeMaxDynamicSharedMemorySize, TC_SMEM_BYTES);
        cudaFuncSetAttribute(k_av_tc,     cudaFuncAttributeMaxDynamicSharedMemorySize, AV_SMEM_BYTES);
        cudaFuncSetAttribute(k_out_tc,    cudaFuncAttributeMaxDynamicSharedMemorySize, TC_SMEM_BYTES);
    }

    // tf32 tensor projections (all four)
    dim3 gptc(DMODEL / 128, (BATCH * SEQ) / 128);   // (4, 64)
    k_proj_tc<<<gptc, 256, TC_SMEM_BYTES>>>(q,       Wq,   bq, p_qu, u, p_qvb, v_bias);
    k_proj_tc<<<gptc, 256, TC_SMEM_BYTES>>>(k,       Wk,   bk, p_kh, nullptr, nullptr, nullptr);
    k_proj_tc<<<gptc, 256, TC_SMEM_BYTES>>>(pos_emb, Wpos, nullptr, p_ph, nullptr, nullptr, nullptr);
    k_proj_tc<<<gptc, 256, TC_SMEM_BYTES>>>(v,       Wv,   bv, p_vh, nullptr, nullptr, nullptr);

    // tf32 tensor score GEMMs (content + pos in one launch)
    dim3 gs(SEQ / 128, SEQ / 128, 2 * BATCH * NHEAD); // (8, 8, 128)
    k_scores_tc<<<gs, 256, TC_SMEM_BYTES>>>(p_qu,  p_kh, out_attn,
                                            p_qvb, p_ph, p_pos);

    k_softmax<<<BATCH * NHEAD * SEQ, 256>>>(out_attn, p_pos, mask);

    // tf32 tensor AV
    dim3 ga(1, SEQ / 128, BATCH * NHEAD);             // (1, 8, 64)
    k_av_tc<<<ga, 256, AV_SMEM_BYTES>>>(out_attn, p_vh, p_ctx);

    // tf32 tensor output projection
    dim3 go(DMODEL / 128, (BATCH * SEQ) / 128);       // (4, 64)
    k_out_tc<<<go, 256, TC_SMEM_BYTES>>>(p_ctx, Wout, bout, out_ctx);
}